// round 8
// baseline (speedup 1.0000x reference)
#include <cuda_runtime.h>
#include <cstdint>
#include <cstddef>

// Problem constants
#define B_   2
#define N_   2048
#define D_   768
#define H_   12
#define HD_  64
#define M_   (B_*N_)      // 4096 rows

// Scratch (device globals)
__device__ float   g_q[B_*H_*N_*HD_];   // [B,H,N,HD] (tf32-valued)
__device__ float   g_k[B_*H_*N_*HD_];
__device__ float   g_v[B_*H_*N_*HD_];
__device__ float   g_o[B_*N_*D_];       // attention out (tf32-valued)
__device__ uint8_t g_d8[(size_t)B_*N_*N_];  // clip(dist) or 32 if masked
__device__ float   g_xr[M_*D_];         // rna-rounded x
__device__ float   g_wqkv[D_*3*D_];     // rna-rounded qkv_w
__device__ float   g_wout[D_*D_];       // rna-rounded out_w

// ---------------------------------------------------------------------------
// helpers
// ---------------------------------------------------------------------------
__device__ __forceinline__ float tf32r(float x) {
    float r; asm("cvt.rna.tf32.f32 %0, %1;" : "=f"(r) : "f"(x)); return r;
}
__device__ __forceinline__ void mma8(float c[4], const uint32_t a[4], const uint32_t b[2]) {
    asm volatile(
        "mma.sync.aligned.m16n8k8.row.col.f32.tf32.tf32.f32 "
        "{%0,%1,%2,%3}, {%4,%5,%6,%7}, {%8,%9}, {%0,%1,%2,%3};"
        : "+f"(c[0]), "+f"(c[1]), "+f"(c[2]), "+f"(c[3])
        : "r"(a[0]), "r"(a[1]), "r"(a[2]), "r"(a[3]), "r"(b[0]), "r"(b[1]));
}
__device__ __forceinline__ void cpa16(void* dst, const void* src) {
    uint32_t a = (uint32_t)__cvta_generic_to_shared(dst);
    asm volatile("cp.async.cg.shared.global [%0], [%1], 16;" :: "r"(a), "l"(src));
}
__device__ __forceinline__ void cpa_commit() { asm volatile("cp.async.commit_group;"); }
__device__ __forceinline__ void cpa_wait0()  { asm volatile("cp.async.wait_group 0;"); }

// ---------------------------------------------------------------------------
// pre-passes
// ---------------------------------------------------------------------------
// dist -> u8 index; masked keys -> index 32 (bias table entry = -1e30)
__global__ __launch_bounds__(256) void pack_dist(const int* __restrict__ dist,
                                                 const int* __restrict__ mask) {
    size_t i = ((size_t)blockIdx.x * 256 + threadIdx.x) * 4;
    int4 v = *(const int4*)(dist + i);
    int b = (int)(i >> 22);            // / (N*N)
    int k = (int)(i & (N_ - 1));       // key index (4-aligned)
    const int* mrow = mask + b * N_ + k;
    uchar4 o;
    o.x = mrow[0] ? 32 : (uint8_t)min(max(v.x, 0), 31);
    o.y = mrow[1] ? 32 : (uint8_t)min(max(v.y, 0), 31);
    o.z = mrow[2] ? 32 : (uint8_t)min(max(v.z, 0), 31);
    o.w = mrow[3] ? 32 : (uint8_t)min(max(v.w, 0), 31);
    *(uchar4*)(g_d8 + i) = o;
}

__global__ __launch_bounds__(256) void round_tf32(const float* __restrict__ src,
                                                  float* __restrict__ dst) {
    size_t i = ((size_t)blockIdx.x * 256 + threadIdx.x) * 4;
    float4 v = *(const float4*)(src + i);
    v.x = tf32r(v.x); v.y = tf32r(v.y); v.z = tf32r(v.z); v.w = tf32r(v.w);
    *(float4*)(dst + i) = v;
}

// ---------------------------------------------------------------------------
// TC GEMM, cp.async double-buffered, 512 threads (16 warps, 4m x 4n).
// C[M x NCOLS] = A[M x 768] @ W + bias. Operands pre-rounded tf32.
// MODE 0: scatter tf32r(C) to g_q/g_k/g_v; MODE 1: A = g_o, plain store.
// ---------------------------------------------------------------------------
template<int NCOLS, int MODE>
__global__ __launch_bounds__(512, 2) void gemm_tc(
    const float* __restrict__ Ain, const float* __restrict__ W,
    const float* __restrict__ bias, float* __restrict__ Cout)
{
    __shared__ float As[2][128][36];
    __shared__ float Bs[2][32][136];

    const float* A = (MODE == 1) ? (const float*)g_o : Ain;

    const int tid  = threadIdx.x;
    const int warp = tid >> 5, lane = tid & 31;
    const int g = lane >> 2, tg = lane & 3;
    const int mw = (warp & 3) << 5;     // 0/32/64/96
    const int nw = (warp >> 2) << 5;    // 0/32/64/96
    const int brow = blockIdx.y << 7;
    const int bcol = blockIdx.x << 7;

    float acc[2][4][4];
    #pragma unroll
    for (int mt = 0; mt < 2; mt++)
        #pragma unroll
        for (int nt = 0; nt < 4; nt++)
            #pragma unroll
            for (int r = 0; r < 4; r++) acc[mt][nt][r] = 0.f;

    auto load_tiles = [&](int buf, int k0) {
        #pragma unroll
        for (int it = 0; it < 2; it++) {
            int idx = tid + (it << 9);
            int r = idx >> 3, c = (idx & 7) << 2;
            cpa16(&As[buf][r][c], A + (size_t)(brow + r) * 768 + k0 + c);
        }
        #pragma unroll
        for (int it = 0; it < 2; it++) {
            int idx = tid + (it << 9);
            int r = idx >> 5, c = (idx & 31) << 2;
            cpa16(&Bs[buf][r][c], W + (size_t)(k0 + r) * NCOLS + bcol + c);
        }
        cpa_commit();
    };

    load_tiles(0, 0);

    for (int kt = 0; kt < 24; kt++) {
        int buf = kt & 1;
        cpa_wait0();
        __syncthreads();
        if (kt + 1 < 24) load_tiles(buf ^ 1, (kt + 1) << 5);

        #pragma unroll
        for (int kk = 0; kk < 32; kk += 8) {
            uint32_t bf[4][2];
            #pragma unroll
            for (int nt = 0; nt < 4; nt++) {
                int col = nw + (nt << 3) + g;
                bf[nt][0] = __float_as_uint(Bs[buf][kk + tg][col]);
                bf[nt][1] = __float_as_uint(Bs[buf][kk + tg + 4][col]);
            }
            #pragma unroll
            for (int mt = 0; mt < 2; mt++) {
                uint32_t af[4];
                int r0 = mw + (mt << 4) + g;
                af[0] = __float_as_uint(As[buf][r0][kk + tg]);
                af[1] = __float_as_uint(As[buf][r0 + 8][kk + tg]);
                af[2] = __float_as_uint(As[buf][r0][kk + tg + 4]);
                af[3] = __float_as_uint(As[buf][r0 + 8][kk + tg + 4]);
                #pragma unroll
                for (int nt = 0; nt < 4; nt++) mma8(acc[mt][nt], af, bf[nt]);
            }
        }
        __syncthreads();
    }

    #pragma unroll
    for (int mt = 0; mt < 2; mt++) {
        #pragma unroll
        for (int nt = 0; nt < 4; nt++) {
            #pragma unroll
            for (int r = 0; r < 4; r++) {
                int row = brow + mw + (mt << 4) + g + ((r >> 1) << 3);
                int col = bcol + nw + (nt << 3) + (tg << 1) + (r & 1);
                float val = acc[mt][nt][r] + bias[col];
                if (MODE == 0) {
                    int which = col / 768;
                    int d = col - which * 768;
                    int h = d >> 6, hd = d & 63;
                    int b = row >> 11, n = row & 2047;
                    float* dst = (which == 0) ? g_q : ((which == 1) ? g_k : g_v);
                    dst[(((size_t)(b * H_ + h)) * N_ + n) * HD_ + hd] = tf32r(val);
                } else {
                    Cout[(size_t)row * NCOLS + col] = val;
                }
            }
        }
    }
}

// ---------------------------------------------------------------------------
// Fused flash attention: 512 threads (16 warps = 4 q-groups x 4 col-quarters),
// tf32 MMA, cp.async double-buffered K/V, dist+mask as u8 index into a
// 33-entry log2-domain bias table. exp2-domain online softmax.
// ---------------------------------------------------------------------------
__global__ __launch_bounds__(512, 2) void attn_tc(
    const float* __restrict__ bias_table)
{
    extern __shared__ float sm[];
    float* Qs   = sm;                          // [64][68]
    float* Ksb  = sm + 4352;                   // 2 x [64][68]
    float* Vsb  = sm + 13056;                  // 2 x [64][72]
    float* Ps   = sm + 22272;                  // [64][68]
    float* sm_m = sm + 26624;                  // [64]
    float* sm_l = sm + 26688;                  // [64]
    float* sm_c = sm + 26752;                  // [64]
    float* bt   = sm + 26816;                  // [33] (log2-scaled; [32] = -1e30)
    // total 26852 floats = 107408 B

    const int tid  = threadIdx.x;
    const int warp = tid >> 5, lane = tid & 31;
    const int g = lane >> 2, tg = lane & 3;
    const int bh = blockIdx.y;
    const int b = bh / H_, h = bh - b * H_;
    const int q0 = blockIdx.x << 6;
    const float scale2 = 0.18033688011112042f;   // 0.125 * log2(e)
    const size_t base = ((size_t)(b * H_ + h)) * N_ * HD_;
    const uint8_t* d8q = g_d8 + ((size_t)(b * N_) + q0) * N_;

    const int qo = (warp & 3) << 4;    // 0/16/32/48
    const int no = (warp >> 2) << 4;   // 0/16/32/48

    if (tid < 64) { sm_m[tid] = -1e30f; sm_l[tid] = 0.f; }
    if (tid < 33)
        bt[tid] = (tid < 32) ? bias_table[tid * H_ + h] * 1.4426950408889634f
                             : -1e30f;

    // Q tile + first K/V tile (one cp.async group); 2048 float4 over 512 thr
    #pragma unroll
    for (int it = 0; it < 2; it++) {
        int idx = tid + (it << 9);
        int r = idx >> 4, c = (idx & 15) << 2;
        cpa16(Qs + r * 68 + c, g_q + base + (size_t)(q0 + r) * HD_ + c);
        cpa16(Ksb + r * 68 + c, g_k + base + (size_t)r * HD_ + c);
        cpa16(Vsb + r * 72 + c, g_v + base + (size_t)r * HD_ + c);
    }
    cpa_commit();

    float o[2][4];
    #pragma unroll
    for (int nt = 0; nt < 2; nt++)
        #pragma unroll
        for (int r = 0; r < 4; r++) o[nt][r] = 0.f;

    for (int t = 0; t < 32; t++) {
        const int buf = t & 1;
        const int k0 = t << 6;
        float* Ks = Ksb + buf * 4352;
        float* Vs = Vsb + buf * 4608;

        cpa_wait0();
        __syncthreads();

        // ---- S = Q K^T (warp covers 16 q-rows x 16 key-cols) ----
        float s[2][4];
        #pragma unroll
        for (int nt = 0; nt < 2; nt++)
            #pragma unroll
            for (int r = 0; r < 4; r++) s[nt][r] = 0.f;
        #pragma unroll
        for (int d = 0; d < 64; d += 8) {
            uint32_t af[4];
            const float* qa = Qs + (qo + g) * 68 + d + tg;
            af[0] = __float_as_uint(qa[0]);
            af[1] = __float_as_uint(qa[8 * 68]);
            af[2] = __float_as_uint(qa[4]);
            af[3] = __float_as_uint(qa[8 * 68 + 4]);
            #pragma unroll
            for (int nt = 0; nt < 2; nt++) {
                uint32_t bfr[2];
                const float* kb = Ks + (no + (nt << 3) + g) * 68 + d + tg;
                bfr[0] = __float_as_uint(kb[0]);
                bfr[1] = __float_as_uint(kb[4]);
                mma8(s[nt], af, bfr);
            }
        }
        #pragma unroll
        for (int nt = 0; nt < 2; nt++) {
            float* p = Ps + (qo + g) * 68 + no + (nt << 3) + (tg << 1);
            p[0] = s[nt][0];          p[1] = s[nt][1];
            p[8 * 68] = s[nt][2];     p[8 * 68 + 1] = s[nt][3];
        }
        __syncthreads();

        // prefetch next K/V during softmax
        if (t + 1 < 32) {
            float* Kn = Ksb + (buf ^ 1) * 4352;
            float* Vn = Vsb + (buf ^ 1) * 4608;
            const size_t koff = base + (size_t)(k0 + 64) * HD_;
            #pragma unroll
            for (int it = 0; it < 2; it++) {
                int idx = tid + (it << 9);
                int r = idx >> 4, c = (idx & 15) << 2;
                cpa16(Kn + r * 68 + c, g_k + koff + (size_t)r * HD_ + c);
                cpa16(Vn + r * 72 + c, g_v + koff + (size_t)r * HD_ + c);
            }
            cpa_commit();
        }

        // ---- online softmax in exp2 domain (4 rows per warp) ----
        {
            const uint8_t* d8t = d8q + k0;
            #pragma unroll
            for (int rr = 0; rr < 4; rr++) {
                int q = (warp << 2) + rr;
                float* pr = Ps + q * 68;
                const uint8_t* dr = d8t + (size_t)q * N_;
                int d0 = __ldg(dr + lane);
                int d1 = __ldg(dr + lane + 32);
                float v0 = pr[lane] * scale2 + bt[d0];
                float v1 = pr[lane + 32] * scale2 + bt[d1];
                float mx = fmaxf(v0, v1);
                #pragma unroll
                for (int off = 16; off; off >>= 1)
                    mx = fmaxf(mx, __shfl_xor_sync(0xffffffffu, mx, off));
                float mold = sm_m[q];
                float mnew = fmaxf(mold, mx);
                float p0 = exp2f(v0 - mnew), p1 = exp2f(v1 - mnew);
                pr[lane] = tf32r(p0);
                pr[lane + 32] = tf32r(p1);
                float ssum = p0 + p1;
                #pragma unroll
                for (int off = 16; off; off >>= 1)
                    ssum += __shfl_xor_sync(0xffffffffu, ssum, off);
                if (lane == 0) {
                    float corr = exp2f(mold - mnew);
                    sm_c[q] = corr; sm_m[q] = mnew;
                    sm_l[q] = sm_l[q] * corr + ssum;
                }
            }
        }
        __syncthreads();

        // ---- rescale O, O += P @ V (warp: 16 q-rows x 16 hd-cols) ----
        float clo = sm_c[qo + g], chi = sm_c[qo + g + 8];
        #pragma unroll
        for (int nt = 0; nt < 2; nt++) {
            o[nt][0] *= clo; o[nt][1] *= clo;
            o[nt][2] *= chi; o[nt][3] *= chi;
        }
        #pragma unroll
        for (int k = 0; k < 64; k += 8) {
            uint32_t af[4];
            const float* pa = Ps + (qo + g) * 68 + k + tg;
            af[0] = __float_as_uint(pa[0]);
            af[1] = __float_as_uint(pa[8 * 68]);
            af[2] = __float_as_uint(pa[4]);
            af[3] = __float_as_uint(pa[8 * 68 + 4]);
            #pragma unroll
            for (int nt = 0; nt < 2; nt++) {
                uint32_t bfr[2];
                const float* vb = Vs + (k + tg) * 72 + no + (nt << 3) + g;
                bfr[0] = __float_as_uint(vb[0]);
                bfr[1] = __float_as_uint(vb[4 * 72]);
                mma8(o[nt], af, bfr);
            }
        }
    }

    // Final normalize + write (tf32-rounded: feeds out-proj MMA as A operand)
    float ilo = 1.f / sm_l[qo + g], ihi = 1.f / sm_l[qo + g + 8];
    #pragma unroll
    for (int nt = 0; nt < 2; nt++) {
        int d = h * HD_ + no + (nt << 3) + (tg << 1);
        float* dst = g_o + ((size_t)(b * N_) + q0 + qo + g) * D_ + d;
        dst[0] = tf32r(o[nt][0] * ilo);
        dst[1] = tf32r(o[nt][1] * ilo);
        dst[8 * D_] = tf32r(o[nt][2] * ihi);
        dst[8 * D_ + 1] = tf32r(o[nt][3] * ihi);
    }
}

// ---------------------------------------------------------------------------
// Launch
// ---------------------------------------------------------------------------
extern "C" void kernel_launch(void* const* d_in, const int* in_sizes, int n_in,
                              void* d_out, int out_size)
{
    const float* x      = (const float*)d_in[0];
    const int*   dist   = (const int*)  d_in[1];
    const int*   mask   = (const int*)  d_in[2];
    const float* qkv_w  = (const float*)d_in[3];
    const float* qkv_b  = (const float*)d_in[4];
    const float* out_w  = (const float*)d_in[5];
    const float* out_b  = (const float*)d_in[6];
    const float* btab   = (const float*)d_in[7];
    float* out = (float*)d_out;

    // pre-passes
    pack_dist<<<(B_ * N_ * N_) / (4 * 256), 256>>>(dist, mask);
    float* xr, *wq, *wo;
    cudaGetSymbolAddress((void**)&xr, g_xr);
    cudaGetSymbolAddress((void**)&wq, g_wqkv);
    cudaGetSymbolAddress((void**)&wo, g_wout);
    round_tf32<<<(M_ * D_) / 1024, 256>>>(x, xr);
    round_tf32<<<(D_ * 3 * D_) / 1024, 256>>>(qkv_w, wq);
    round_tf32<<<(D_ * D_) / 1024, 256>>>(out_w, wo);

    // QKV projection
    gemm_tc<3 * D_, 0><<<dim3((3 * D_) / 128, M_ / 128), 512>>>(
        xr, wq, qkv_b, nullptr);

    // fused attention
    const int ATTN_SMEM = 26852 * 4;  // 107408 B
    cudaFuncSetAttribute(attn_tc,
                         cudaFuncAttributeMaxDynamicSharedMemorySize, ATTN_SMEM);
    attn_tc<<<dim3(N_ / 64, B_ * H_), 512, ATTN_SMEM>>>(btab);

    // output projection
    gemm_tc<D_, 1><<<dim3(D_ / 128, M_ / 128), 512>>>(
        nullptr, wo, out_b, out);
}